// round 1
// baseline (speedup 1.0000x reference)
#include <cuda_runtime.h>
#include <cstdint>
#include <math.h>

#define NTOK 8192
#define DIM  1024
#define HID  256
#define HIDC 128
#define POOL 16384
#define TOPK 1024

// ---------------- scratch (device globals: no allocations allowed) ----------
__device__ float g_hs[NTOK * HID];                 // 8 MB
__device__ float g_hc[NTOK * HIDC];                // 4 MB
__device__ float g_scores[(size_t)NTOK * POOL];    // 512 MB
__device__ int   g_budget[NTOK];

// ---------------- fp32 tiled GEMM: C = (relu?)(A[MxK] @ B[KxN] + bias[N]) ---
template<bool RELU>
__global__ void __launch_bounds__(256, 2)
sgemm_bias(const float* __restrict__ A, const float* __restrict__ B,
           const float* __restrict__ bias, float* __restrict__ C,
           int M, int N, int K)
{
    __shared__ float As[8][128];
    __shared__ float Bs[8][128];

    const int tid = threadIdx.x;              // 256 threads
    const int bm  = blockIdx.y * 128;
    const int bn  = blockIdx.x * 128;
    const int tx  = tid & 15;                 // 16 cols of threads
    const int ty  = tid >> 4;                 // 16 rows of threads

    float acc[8][8];
#pragma unroll
    for (int i = 0; i < 8; i++)
#pragma unroll
        for (int j = 0; j < 8; j++) acc[i][j] = 0.f;

    for (int k0 = 0; k0 < K; k0 += 8) {
        // load A tile 128x8 (transposed into As[k][m])
        {
            int r  = tid >> 1;
            int c4 = (tid & 1) * 4;
            float4 v = *(const float4*)(A + (size_t)(bm + r) * K + k0 + c4);
            As[c4 + 0][r] = v.x; As[c4 + 1][r] = v.y;
            As[c4 + 2][r] = v.z; As[c4 + 3][r] = v.w;
        }
        // load B tile 8x128
        {
            int r  = tid >> 5;
            int c4 = (tid & 31) * 4;
            float4 v = *(const float4*)(B + (size_t)(k0 + r) * N + bn + c4);
            *(float4*)&Bs[r][c4] = v;
        }
        __syncthreads();

#pragma unroll
        for (int k = 0; k < 8; k++) {
            float a[8], b[8];
            *(float4*)&a[0] = *(const float4*)&As[k][ty * 8];
            *(float4*)&a[4] = *(const float4*)&As[k][ty * 8 + 4];
            *(float4*)&b[0] = *(const float4*)&Bs[k][tx * 8];
            *(float4*)&b[4] = *(const float4*)&Bs[k][tx * 8 + 4];
#pragma unroll
            for (int i = 0; i < 8; i++)
#pragma unroll
                for (int j = 0; j < 8; j++)
                    acc[i][j] += a[i] * b[j];
        }
        __syncthreads();
    }

#pragma unroll
    for (int i = 0; i < 8; i++) {
        int row = bm + ty * 8 + i;
        float* cp = C + (size_t)row * N + bn + tx * 8;
#pragma unroll
        for (int j = 0; j < 8; j++) {
            float v = acc[i][j] + bias[bn + tx * 8 + j];
            if (RELU) v = fmaxf(v, 0.f);
            cp[j] = v;
        }
    }
}

// ---------------- complexity -> sigmoid -> budget ---------------------------
__global__ void complexity_kernel(const float* __restrict__ hc,
                                  const float* __restrict__ w2c,
                                  const float* __restrict__ b2c,
                                  float* __restrict__ out_c,
                                  int* __restrict__ budget)
{
    int warp = (blockIdx.x * blockDim.x + threadIdx.x) >> 5;
    int lane = threadIdx.x & 31;
    if (warp >= NTOK) return;
    const float* h = hc + (size_t)warp * HIDC;
    float s = 0.f;
#pragma unroll
    for (int i = lane; i < HIDC; i += 32) s += h[i] * w2c[i];
#pragma unroll
    for (int o = 16; o; o >>= 1) s += __shfl_xor_sync(0xFFFFFFFFu, s, o);
    if (lane == 0) {
        float z = s + b2c[0];
        float c = 1.f / (1.f + expf(-z));
        out_c[warp] = c;
        float raw = 100.f + 924.f * (c * c);          // MIN + (MAX-MIN)*c^2
        raw = fminf(fmaxf(raw, 100.f), 1024.f);
        budget[warp] = (int)rintf(raw);                // round-half-even == jnp.round
    }
}

// ---------------- per-token top-1024 (sorted) + softmax + mask --------------
__device__ __forceinline__ uint32_t f2mk(float f) {
    uint32_t u = __float_as_uint(f);
    return (u & 0x80000000u) ? ~u : (u | 0x80000000u);
}
__device__ __forceinline__ float mk2f(uint32_t mk) {
    uint32_t u = (mk & 0x80000000u) ? (mk ^ 0x80000000u) : ~mk;
    return __uint_as_float(u);
}

__global__ void __launch_bounds__(256)
topk_kernel(const float* __restrict__ scores, const int* __restrict__ budget,
            float* __restrict__ out_idx, float* __restrict__ out_w,
            float* __restrict__ out_m)
{
    __shared__ uint32_t hist[4096];
    __shared__ unsigned long long pairs[2048];
    __shared__ uint32_t chunksum[256];
    __shared__ uint32_t s_bstar, s_cnt;
    __shared__ float    s_red[256];

    const int t   = blockIdx.x;
    const int tid = threadIdx.x;
    const float* row = scores + (size_t)t * POOL;

    for (int i = tid; i < 4096; i += 256) hist[i] = 0;
    __syncthreads();

    // pass 1: 12-bit monotonic-key histogram
    for (int i = tid; i < POOL; i += 256)
        atomicAdd(&hist[f2mk(row[i]) >> 20], 1u);
    __syncthreads();

    uint32_t cs = 0;
#pragma unroll
    for (int b = tid * 16; b < tid * 16 + 16; b++) cs += hist[b];
    chunksum[tid] = cs;
    __syncthreads();

    if (tid == 0) {
        uint32_t acc = 0;
        int chunk = 255;
        for (; chunk > 0; chunk--) {
            if (acc + chunksum[chunk] >= TOPK) break;
            acc += chunksum[chunk];
        }
        int b = chunk * 16 + 15;
        for (; b > chunk * 16; b--) {
            if (acc + hist[b] >= TOPK) break;
            acc += hist[b];
        }
        s_bstar = (uint32_t)b;
        s_cnt   = 0;
    }
    __syncthreads();
    const uint32_t bstar = s_bstar;

    // pass 2: compact survivors (bin >= bstar), packed key: desc value, asc idx
    for (int i = tid; i < POOL; i += 256) {
        uint32_t mk = f2mk(row[i]);
        if ((mk >> 20) >= bstar) {
            uint32_t pos = atomicAdd(&s_cnt, 1u);
            if (pos < 2048)
                pairs[pos] = ((unsigned long long)mk << 32) |
                             (unsigned long long)(0xFFFFFFFFu - (uint32_t)i);
        }
    }
    __syncthreads();
    uint32_t cnt = s_cnt > 2048 ? 2048u : s_cnt;
    for (int i = tid; i < 2048; i += 256)
        if ((uint32_t)i >= cnt) pairs[i] = 0ull;
    __syncthreads();

    // bitonic sort 2048 u64, descending
    for (int k = 2; k <= 2048; k <<= 1) {
        for (int j = k >> 1; j > 0; j >>= 1) {
            for (int i = tid; i < 2048; i += 256) {
                int ixj = i ^ j;
                if (ixj > i) {
                    unsigned long long a = pairs[i], b = pairs[ixj];
                    bool desc = ((i & k) == 0);
                    if (desc ? (a < b) : (a > b)) { pairs[i] = b; pairs[ixj] = a; }
                }
            }
            __syncthreads();
        }
    }

    // softmax over top-1024 (sorted desc -> max is element 0)
    const float vmax = mk2f((uint32_t)(pairs[0] >> 32));
    float myexp[4];
    float psum = 0.f;
#pragma unroll
    for (int r = 0; r < 4; r++) {
        int jj = tid + r * 256;
        float v = mk2f((uint32_t)(pairs[jj] >> 32));
        myexp[r] = expf(v - vmax);
        psum += myexp[r];
    }
    s_red[tid] = psum;
    __syncthreads();
    for (int o = 128; o; o >>= 1) {
        if (tid < o) s_red[tid] += s_red[tid + o];
        __syncthreads();
    }
    const float inv = 1.f / s_red[0];

    const int bud = budget[t];
    const size_t base = (size_t)t * TOPK;
#pragma unroll
    for (int r = 0; r < 4; r++) {
        int jj = tid + r * 256;
        unsigned long long p = pairs[jj];
        uint32_t idx = 0xFFFFFFFFu - (uint32_t)(p & 0xFFFFFFFFull);
        float m = (jj < bud) ? 1.f : 0.f;
        out_idx[base + jj] = (float)idx;
        out_w[base + jj]   = myexp[r] * inv * m;
        out_m[base + jj]   = m;
    }
}

// ---------------- launch -----------------------------------------------------
extern "C" void kernel_launch(void* const* d_in, const int* in_sizes, int n_in,
                              void* d_out, int out_size)
{
    const float* x   = (const float*)d_in[0];
    const float* w1c = (const float*)d_in[1];
    const float* b1c = (const float*)d_in[2];
    const float* w2c = (const float*)d_in[3];
    const float* b2c = (const float*)d_in[4];
    const float* ws1 = (const float*)d_in[5];
    const float* bs1 = (const float*)d_in[6];
    const float* ws2 = (const float*)d_in[7];
    const float* bs2 = (const float*)d_in[8];

    float* out     = (float*)d_out;
    float* out_idx = out;
    float* out_w   = out + (size_t)NTOK * TOPK;
    float* out_m   = out + 2 * (size_t)NTOK * TOPK;
    float* out_c   = out + 3 * (size_t)NTOK * TOPK;

    float *hs_p, *hc_p, *sc_p;
    int   *bud_p;
    cudaGetSymbolAddress((void**)&hs_p,  g_hs);
    cudaGetSymbolAddress((void**)&hc_p,  g_hc);
    cudaGetSymbolAddress((void**)&sc_p,  g_scores);
    cudaGetSymbolAddress((void**)&bud_p, g_budget);

    dim3 blk(256);
    // hs = relu(x @ ws1 + bs1)
    sgemm_bias<true><<<dim3(HID / 128, NTOK / 128), blk>>>(x, ws1, bs1, hs_p, NTOK, HID, DIM);
    // hc = relu(x @ w1c + b1c)
    sgemm_bias<true><<<dim3(HIDC / 128, NTOK / 128), blk>>>(x, w1c, b1c, hc_p, NTOK, HIDC, DIM);
    // complexity + budgets
    complexity_kernel<<<NTOK / 8, 256>>>(hc_p, w2c, b2c, out_c, bud_p);
    // scores = hs @ ws2 + bs2
    sgemm_bias<false><<<dim3(POOL / 128, NTOK / 128), blk>>>(hs_p, ws2, bs2, sc_p, NTOK, POOL, HID);
    // per-token sorted top-k + softmax + mask
    topk_kernel<<<NTOK, 256>>>(sc_p, bud_p, out_idx, out_w, out_m);
}

// round 2
// speedup vs baseline: 1.2489x; 1.2489x over previous
#include <cuda_runtime.h>
#include <cstdint>
#include <math.h>

#define NTOK 8192
#define DIM  1024
#define HID  256
#define HIDC 128
#define POOL 16384
#define TOPK 1024

// ---------------- scratch (device globals: no allocations allowed) ----------
__device__ float g_hs[NTOK * HID];                 // 8 MB
__device__ float g_hc[NTOK * HIDC];                // 4 MB
__device__ float g_scores[(size_t)NTOK * POOL];    // 512 MB
__device__ int   g_budget[NTOK];

// packed fp32x2 FMA (sm_100+): two independent rn-rounded fp32 FMAs per issue.
__device__ __forceinline__ float2 ffma2(float2 a, float2 b, float2 c) {
    unsigned long long A = *(unsigned long long*)&a;
    unsigned long long B = *(unsigned long long*)&b;
    unsigned long long C = *(unsigned long long*)&c;
    unsigned long long D;
    asm("fma.rn.f32x2 %0, %1, %2, %3;" : "=l"(D) : "l"(A), "l"(B), "l"(C));
    return *(float2*)&D;
}

// ---------------- fp32x2 tiled GEMM: C = (relu?)(A[MxK] @ B[KxN] + bias[N]) --
// BM=128, BN=128, BK=8, 256 threads, per-thread 8x8 outputs (4 float2x2 groups)
// Thread (tx,ty): rows ty*8..ty*8+7, cols {tx*4 + g*64 + 0..3} for g in {0,1}.
// Accumulation: each output element is ONE fp32 FMA chain in increasing k-order
// -> bitwise-identical to scalar sequential accumulation (matches BLAS).
template<bool RELU>
__global__ void __launch_bounds__(256, 2)
sgemm2_bias(const float* __restrict__ A, const float* __restrict__ B,
            const float* __restrict__ bias, float* __restrict__ C,
            int M, int N, int K)
{
    __shared__ float As[2][8][128];
    __shared__ float Bs[2][8][128];

    const int tid = threadIdx.x;
    const int bm  = blockIdx.y * 128;
    const int bn  = blockIdx.x * 128;
    const int tx  = tid & 15;
    const int ty  = tid >> 4;

    float2 acc[8][4];
#pragma unroll
    for (int i = 0; i < 8; i++)
#pragma unroll
        for (int q = 0; q < 4; q++) acc[i][q] = make_float2(0.f, 0.f);

    // staging pointers
    const int ar = tid >> 1;            // A row within tile (0..127)
    const int ac = (tid & 1) * 4;       // A k-col group (0 or 4)
    const int br = tid >> 5;            // B k-row (0..7)
    const int bc = (tid & 31) * 4;      // B col group (0..124)
    const float* Aptr = A + (size_t)(bm + ar) * K + ac;
    const float* Bptr = B + (size_t)br * N + bn + bc;

    const int NT = K >> 3;

    // prologue: tile 0
    float4 av = *(const float4*)(Aptr);
    float4 bv = *(const float4*)(Bptr);
    As[0][ac + 0][ar] = av.x; As[0][ac + 1][ar] = av.y;
    As[0][ac + 2][ar] = av.z; As[0][ac + 3][ar] = av.w;
    *(float4*)&Bs[0][br][bc] = bv;
    __syncthreads();

    for (int t = 0; t < NT; t++) {
        const int buf = t & 1;
        const bool more = (t + 1) < NT;
        if (more) {
            av = *(const float4*)(Aptr + (t + 1) * 8);
            bv = *(const float4*)(Bptr + (size_t)(t + 1) * 8 * N);
        }

#pragma unroll
        for (int k = 0; k < 8; k++) {
            float4 a0 = *(const float4*)&As[buf][k][ty * 8];
            float4 a1 = *(const float4*)&As[buf][k][ty * 8 + 4];
            float4 b0 = *(const float4*)&Bs[buf][k][tx * 4];
            float4 b1 = *(const float4*)&Bs[buf][k][tx * 4 + 64];
            float2 bp[4];
            bp[0] = make_float2(b0.x, b0.y); bp[1] = make_float2(b0.z, b0.w);
            bp[2] = make_float2(b1.x, b1.y); bp[3] = make_float2(b1.z, b1.w);
            float a[8] = {a0.x, a0.y, a0.z, a0.w, a1.x, a1.y, a1.z, a1.w};
#pragma unroll
            for (int i = 0; i < 8; i++) {
                float2 ad = make_float2(a[i], a[i]);
#pragma unroll
                for (int q = 0; q < 4; q++)
                    acc[i][q] = ffma2(ad, bp[q], acc[i][q]);
            }
        }

        if (more) {
            const int nb = buf ^ 1;
            As[nb][ac + 0][ar] = av.x; As[nb][ac + 1][ar] = av.y;
            As[nb][ac + 2][ar] = av.z; As[nb][ac + 3][ar] = av.w;
            *(float4*)&Bs[nb][br][bc] = bv;
        }
        __syncthreads();
    }

    // epilogue: bias (+relu), float4 stores
#pragma unroll
    for (int i = 0; i < 8; i++) {
        const int row = bm + ty * 8 + i;
#pragma unroll
        for (int g = 0; g < 2; g++) {
            const int col = bn + tx * 4 + g * 64;
            float4 v;
            v.x = acc[i][g * 2 + 0].x + bias[col + 0];
            v.y = acc[i][g * 2 + 0].y + bias[col + 1];
            v.z = acc[i][g * 2 + 1].x + bias[col + 2];
            v.w = acc[i][g * 2 + 1].y + bias[col + 3];
            if (RELU) {
                v.x = fmaxf(v.x, 0.f); v.y = fmaxf(v.y, 0.f);
                v.z = fmaxf(v.z, 0.f); v.w = fmaxf(v.w, 0.f);
            }
            *(float4*)(C + (size_t)row * N + col) = v;
        }
    }
}

// ---------------- complexity -> sigmoid -> budget ---------------------------
__global__ void complexity_kernel(const float* __restrict__ hc,
                                  const float* __restrict__ w2c,
                                  const float* __restrict__ b2c,
                                  float* __restrict__ out_c,
                                  int* __restrict__ budget)
{
    int warp = (blockIdx.x * blockDim.x + threadIdx.x) >> 5;
    int lane = threadIdx.x & 31;
    if (warp >= NTOK) return;
    const float* h = hc + (size_t)warp * HIDC;
    float s = 0.f;
#pragma unroll
    for (int i = lane; i < HIDC; i += 32) s += h[i] * w2c[i];
#pragma unroll
    for (int o = 16; o; o >>= 1) s += __shfl_xor_sync(0xFFFFFFFFu, s, o);
    if (lane == 0) {
        float z = s + b2c[0];
        float c = 1.f / (1.f + expf(-z));
        out_c[warp] = c;
        float raw = 100.f + 924.f * (c * c);
        raw = fminf(fmaxf(raw, 100.f), 1024.f);
        budget[warp] = (int)rintf(raw);
    }
}

// ---------------- per-token top-1024 (sorted) + softmax + mask --------------
__device__ __forceinline__ uint32_t f2mk(float f) {
    uint32_t u = __float_as_uint(f);
    return (u & 0x80000000u) ? ~u : (u | 0x80000000u);
}
__device__ __forceinline__ float mk2f(uint32_t mk) {
    uint32_t u = (mk & 0x80000000u) ? (mk ^ 0x80000000u) : ~mk;
    return __uint_as_float(u);
}

__global__ void __launch_bounds__(512)
topk_kernel(const float* __restrict__ scores, const int* __restrict__ budget,
            float* __restrict__ out_idx, float* __restrict__ out_w,
            float* __restrict__ out_m)
{
    __shared__ uint32_t hist[4096];
    __shared__ unsigned long long pairs[2048];
    __shared__ uint32_t chunksum[256];
    __shared__ uint32_t s_bstar, s_cnt;
    __shared__ float    s_red[512];

    const int t   = blockIdx.x;
    const int tid = threadIdx.x;
    const float* row = scores + (size_t)t * POOL;
    const float4* row4 = (const float4*)row;

    for (int i = tid; i < 4096; i += 512) hist[i] = 0;
    __syncthreads();

    // pass 1: 12-bit monotonic-key histogram (float4 loads)
#pragma unroll
    for (int s = 0; s < 8; s++) {
        float4 v = row4[tid + s * 512];
        atomicAdd(&hist[f2mk(v.x) >> 20], 1u);
        atomicAdd(&hist[f2mk(v.y) >> 20], 1u);
        atomicAdd(&hist[f2mk(v.z) >> 20], 1u);
        atomicAdd(&hist[f2mk(v.w) >> 20], 1u);
    }
    __syncthreads();

    if (tid < 256) {
        uint32_t cs = 0;
#pragma unroll
        for (int b = tid * 16; b < tid * 16 + 16; b++) cs += hist[b];
        chunksum[tid] = cs;
    }
    __syncthreads();

    if (tid == 0) {
        uint32_t acc = 0;
        int chunk = 255;
        for (; chunk > 0; chunk--) {
            if (acc + chunksum[chunk] >= TOPK) break;
            acc += chunksum[chunk];
        }
        int b = chunk * 16 + 15;
        for (; b > chunk * 16; b--) {
            if (acc + hist[b] >= TOPK) break;
            acc += hist[b];
        }
        s_bstar = (uint32_t)b;
        s_cnt   = 0;
    }
    __syncthreads();
    const uint32_t bstar = s_bstar;

    // pass 2: compact survivors; packed key: desc value, asc index
#pragma unroll
    for (int s = 0; s < 8; s++) {
        int i4 = tid + s * 512;
        float4 v = row4[i4];
        float vals[4] = {v.x, v.y, v.z, v.w};
#pragma unroll
        for (int e = 0; e < 4; e++) {
            uint32_t mk = f2mk(vals[e]);
            if ((mk >> 20) >= bstar) {
                uint32_t pos = atomicAdd(&s_cnt, 1u);
                if (pos < 2048) {
                    uint32_t idx = (uint32_t)(i4 * 4 + e);
                    pairs[pos] = ((unsigned long long)mk << 32) |
                                 (unsigned long long)(0xFFFFFFFFu - idx);
                }
            }
        }
    }
    __syncthreads();
    uint32_t cnt = s_cnt > 2048 ? 2048u : s_cnt;
    for (int i = tid; i < 2048; i += 512)
        if ((uint32_t)i >= cnt) pairs[i] = 0ull;
    __syncthreads();

    // bitonic sort 2048 u64, descending
    for (int k = 2; k <= 2048; k <<= 1) {
        for (int j = k >> 1; j > 0; j >>= 1) {
            for (int i = tid; i < 2048; i += 512) {
                int ixj = i ^ j;
                if (ixj > i) {
                    unsigned long long a = pairs[i], b = pairs[ixj];
                    bool desc = ((i & k) == 0);
                    if (desc ? (a < b) : (a > b)) { pairs[i] = b; pairs[ixj] = a; }
                }
            }
            __syncthreads();
        }
    }

    // softmax over sorted top-1024
    const float vmax = mk2f((uint32_t)(pairs[0] >> 32));
    float myexp[2];
    float psum = 0.f;
#pragma unroll
    for (int r = 0; r < 2; r++) {
        int jj = tid + r * 512;
        float v = mk2f((uint32_t)(pairs[jj] >> 32));
        myexp[r] = expf(v - vmax);
        psum += myexp[r];
    }
    s_red[tid] = psum;
    __syncthreads();
    for (int o = 256; o; o >>= 1) {
        if (tid < o) s_red[tid] += s_red[tid + o];
        __syncthreads();
    }
    const float inv = 1.f / s_red[0];

    const int bud = budget[t];
    const size_t base = (size_t)t * TOPK;
#pragma unroll
    for (int r = 0; r < 2; r++) {
        int jj = tid + r * 512;
        unsigned long long p = pairs[jj];
        uint32_t idx = 0xFFFFFFFFu - (uint32_t)(p & 0xFFFFFFFFull);
        float m = (jj < bud) ? 1.f : 0.f;
        out_idx[base + jj] = (float)idx;
        out_w[base + jj]   = myexp[r] * inv * m;
        out_m[base + jj]   = m;
    }
}

// ---------------- launch -----------------------------------------------------
extern "C" void kernel_launch(void* const* d_in, const int* in_sizes, int n_in,
                              void* d_out, int out_size)
{
    const float* x   = (const float*)d_in[0];
    const float* w1c = (const float*)d_in[1];
    const float* b1c = (const float*)d_in[2];
    const float* w2c = (const float*)d_in[3];
    const float* b2c = (const float*)d_in[4];
    const float* ws1 = (const float*)d_in[5];
    const float* bs1 = (const float*)d_in[6];
    const float* ws2 = (const float*)d_in[7];
    const float* bs2 = (const float*)d_in[8];

    float* out     = (float*)d_out;
    float* out_idx = out;
    float* out_w   = out + (size_t)NTOK * TOPK;
    float* out_m   = out + 2 * (size_t)NTOK * TOPK;
    float* out_c   = out + 3 * (size_t)NTOK * TOPK;

    float *hs_p, *hc_p, *sc_p;
    int   *bud_p;
    cudaGetSymbolAddress((void**)&hs_p,  g_hs);
    cudaGetSymbolAddress((void**)&hc_p,  g_hc);
    cudaGetSymbolAddress((void**)&sc_p,  g_scores);
    cudaGetSymbolAddress((void**)&bud_p, g_budget);

    dim3 blk(256);
    // hs = relu(x @ ws1 + bs1)
    sgemm2_bias<true><<<dim3(HID / 128, NTOK / 128), blk>>>(x, ws1, bs1, hs_p, NTOK, HID, DIM);
    // hc = relu(x @ w1c + b1c)
    sgemm2_bias<true><<<dim3(HIDC / 128, NTOK / 128), blk>>>(x, w1c, b1c, hc_p, NTOK, HIDC, DIM);
    // complexity + budgets
    complexity_kernel<<<NTOK / 8, 256>>>(hc_p, w2c, b2c, out_c, bud_p);
    // scores = hs @ ws2 + bs2
    sgemm2_bias<false><<<dim3(POOL / 128, NTOK / 128), blk>>>(hs_p, ws2, bs2, sc_p, NTOK, POOL, HID);
    // per-token sorted top-k + softmax + mask
    topk_kernel<<<NTOK, 512>>>(sc_p, bud_p, out_idx, out_w, out_m);
}